// round 15
// baseline (speedup 1.0000x reference)
#include <cuda_runtime.h>
#include <cuda_fp16.h>
#include <math.h>
#include <cstdint>

#define NTOK 4096
#define DDIM 512
#define HDIM 2048
#define NEXP 8
#define NC 7
#define BETA_FIXED (1.0f/3.0f)
#define BETA_DYN   (2.0f/3.0f)

// ================= scratch (static device globals) =================
__device__ __half g_xa[NTOK * DDIM];                 // activations fp16
__device__ __half g_w1[NEXP * DDIM * HDIM];          // [E][D][H] fp16
__device__ __half g_w2[NEXP * HDIM * DDIM];          // [E][H][D] fp16
__device__ __half g_ha[(size_t)NEXP * NTOK * HDIM];  // hidden fp16
__device__ float g_Y[(size_t)NEXP * NTOK * DDIM];
__device__ int   g_list[NEXP * NTOK];
__device__ float g_scale[NEXP * NTOK];
__device__ int   g_pos[NTOK * 2];
__device__ int   g_cnt[NEXP];    // zero at module load; k_combine re-zeroes after use
__device__ float g_imp[NC];      // idem

// ================= helpers =================
__device__ __forceinline__ uint32_t smem_u32(const void* p) {
    uint32_t a;
    asm("{ .reg .u64 t; cvta.to.shared.u64 t, %1; cvt.u32.u64 %0, t; }" : "=r"(a) : "l"(p));
    return a;
}
__device__ __forceinline__ void cpa16(uint32_t dst, const void* src) {
    asm volatile("cp.async.cg.shared.global [%0], [%1], 16;" :: "r"(dst), "l"(src));
}
#define CPA_COMMIT() asm volatile("cp.async.commit_group;" ::: "memory")
#define CPA_WAIT1()  asm volatile("cp.async.wait_group 1;" ::: "memory")

__device__ __forceinline__ void ldm_x4(uint32_t addr, uint32_t* r) {
    asm volatile("ldmatrix.sync.aligned.m8n8.x4.shared.b16 {%0,%1,%2,%3}, [%4];"
        : "=r"(r[0]), "=r"(r[1]), "=r"(r[2]), "=r"(r[3]) : "r"(addr));
}
__device__ __forceinline__ void ldm_x4t(uint32_t addr, uint32_t* r) {
    asm volatile("ldmatrix.sync.aligned.m8n8.x4.trans.shared.b16 {%0,%1,%2,%3}, [%4];"
        : "=r"(r[0]), "=r"(r[1]), "=r"(r[2]), "=r"(r[3]) : "r"(addr));
}
__device__ __forceinline__ void mma16816(float* c, const uint32_t* a, uint32_t b0, uint32_t b1) {
    asm volatile("mma.sync.aligned.m16n8k16.row.col.f32.f16.f16.f32 "
        "{%0,%1,%2,%3}, {%4,%5,%6,%7}, {%8,%9}, {%0,%1,%2,%3};"
        : "+f"(c[0]), "+f"(c[1]), "+f"(c[2]), "+f"(c[3])
        : "r"(a[0]), "r"(a[1]), "r"(a[2]), "r"(a[3]), "r"(b0), "r"(b1));
}
__device__ __forceinline__ uint32_t pack2h(__half a, __half b) {
    return ((uint32_t)__half_as_ushort(b) << 16) | __half_as_ushort(a);
}
__device__ __forceinline__ uint4 cvt8(float4 v0, float4 v1) {
    uint4 p;
    p.x = pack2h(__float2half(v0.x), __float2half(v0.y));
    p.y = pack2h(__float2half(v0.z), __float2half(v0.w));
    p.z = pack2h(__float2half(v1.x), __float2half(v1.y));
    p.w = pack2h(__float2half(v1.z), __float2half(v1.w));
    return p;
}

// ===== tiles: BM=64 both gemms =====
#define RSBA 144
#define RSBB 272
#define RSBB2 144
#define BM 64
#define OFF_A  0
#define OFF_B  (BM * RSBA)                       // 9216
#define STAGE1 (BM * RSBA + 64 * RSBB)           // 26624
#define STAGE2 (BM * RSBA + 64 * RSBB2)          // 18432
#define NSTG 3
#define SM_TILES 1024
#define SMEM1 (SM_TILES + NSTG * STAGE1)         // 80896 -> 2 CTAs/SM
#define SMEM2 (SM_TILES + NSTG * STAGE2)         // 56320 -> 2 CTAs/SM

#define W1_ELEMS (NEXP * DDIM * HDIM)
#define W2_ELEMS (NEXP * HDIM * DDIM)
#define RTR_BLOCKS (NTOK / 8)                    // 512
#define CVT1_BLOCKS 1024

// ================= fused prep: router (+x->fp16) | W1 fp32->fp16 =============
__global__ void k_prep(const float* __restrict__ x,
                       const float* __restrict__ rW,
                       const float* __restrict__ rb,
                       const float4* __restrict__ W1,
                       float* __restrict__ out, long out_size) {
    int t = threadIdx.x;
    if (blockIdx.x >= RTR_BLOCKS) {
        int idx = (blockIdx.x - RTR_BLOCKS) * blockDim.x + t;
        const int TOT = W1_ELEMS / 8;
        for (int i = idx; i < TOT; i += CVT1_BLOCKS * 256)
            ((uint4*)g_w1)[i] = cvt8(W1[2 * i], W1[2 * i + 1]);
        return;
    }

    __shared__ float imp_s[NC];
    if (t < NC) imp_s[t] = 0.f;
    __syncthreads();

    int w = t >> 5, lane = t & 31;
    int n = blockIdx.x * 8 + w;

    float acc[NC];
#pragma unroll
    for (int j = 0; j < NC; j++) acc[j] = 0.f;

    const float* xr = x + (size_t)n * DDIM;
    __half* xout = g_xa + (size_t)n * DDIM;
    for (int k = lane; k < DDIM; k += 32) {
        float xv = xr[k];
        xout[k] = __float2half(xv);
        const float* wr = rW + (size_t)k * NC;
#pragma unroll
        for (int j = 0; j < NC; j++) acc[j] += xv * wr[j];
    }
#pragma unroll
    for (int j = 0; j < NC; j++) {
#pragma unroll
        for (int off = 16; off > 0; off >>= 1)
            acc[j] += __shfl_xor_sync(0xffffffffu, acc[j], off);
        acc[j] += rb[j];
    }

    if (lane == 0) {
        float m = acc[0];
#pragma unroll
        for (int j = 1; j < NC; j++) m = fmaxf(m, acc[j]);
        float p[NC], s = 0.f;
#pragma unroll
        for (int j = 0; j < NC; j++) { p[j] = __expf(acc[j] - m); s += p[j]; }
        float inv = 1.f / s;
#pragma unroll
        for (int j = 0; j < NC; j++) atomicAdd(&imp_s[j], p[j] * inv);

        int i1 = 0;
#pragma unroll
        for (int j = 1; j < NC; j++) if (acc[j] > acc[i1]) i1 = j;
        int i2 = (i1 == 0) ? 1 : 0;
#pragma unroll
        for (int j = 0; j < NC; j++) if (j != i1 && acc[j] > acc[i2]) i2 = j;

        float e2 = __expf(acc[i2] - acc[i1]);
        float den = 1.f / (1.f + e2);
        float gA = den, gB = e2 * den;

        int eA = i1 + 1, eB = i2 + 1;
        int rA = atomicAdd(&g_cnt[eA], 1);
        int rB = atomicAdd(&g_cnt[eB], 1);
        int rowA = eA * NTOK + rA;
        int rowB = eB * NTOK + rB;
        g_list[rowA] = n;  g_list[rowB] = n;
        g_scale[rowA] = BETA_DYN * gA;
        g_scale[rowB] = BETA_DYN * gB;
        g_pos[2 * n]     = rowA;
        g_pos[2 * n + 1] = rowB;

        long selbase = (long)NTOK * DDIM + 2;
        if (selbase + 2 * (long)NTOK <= out_size) {
            out[selbase + 2 * n]     = (float)eA;
            out[selbase + 2 * n + 1] = (float)eB;
        }
    }
    __syncthreads();
    if (t < NC) atomicAdd(&g_imp[t], imp_s[t]);
}

// ================= gemm1 compute: warp tile 32x64 =================
__device__ __forceinline__ void gemm1_chunk(
    uint32_t tb, int wm, int wn, int lane, float acc[2][8][4])
{
    uint32_t a_row = (uint32_t)((lane & 7) + ((lane >> 3) & 1) * 8);
    uint32_t a_kh  = (uint32_t)(lane >> 4);
    uint32_t a_base = tb + OFF_A + (wm * 32 + a_row) * RSBA + a_kh * 16;

    uint32_t grp = (uint32_t)(lane >> 3), sub = (uint32_t)(lane & 7);
    uint32_t k_loc = (grp & 1) * 8 + sub;
    uint32_t n_loc = (grp >> 1) * 8;
    uint32_t b_base = tb + OFF_B + k_loc * RSBB + (wn * 64 + n_loc) * 2;

#pragma unroll
    for (int kk = 0; kk < 4; kk++) {
        uint32_t ah[2][4];
#pragma unroll
        for (int mf = 0; mf < 2; mf++)
            ldm_x4(a_base + mf * 16 * RSBA + kk * 32, ah[mf]);
#pragma unroll
        for (int p = 0; p < 4; p++) {
            uint32_t br[4];
            ldm_x4t(b_base + kk * 16 * RSBB + p * 32, br);
#pragma unroll
            for (int q = 0; q < 2; q++) {
                int ni = p * 2 + q;
#pragma unroll
                for (int mi = 0; mi < 2; mi++)
                    mma16816(acc[mi][ni], ah[mi], br[2 * q], br[2 * q + 1]);
            }
        }
    }
}

// ================= gemm2 compute: warp tile 32x32 =================
__device__ __forceinline__ void gemm2_chunk(
    uint32_t tb, int wm, int wn, int lane, float acc[2][4][4])
{
    uint32_t a_row = (uint32_t)((lane & 7) + ((lane >> 3) & 1) * 8);
    uint32_t a_kh  = (uint32_t)(lane >> 4);
    uint32_t a_base = tb + OFF_A + (wm * 32 + a_row) * RSBA + a_kh * 16;

    uint32_t grp = (uint32_t)(lane >> 3), sub = (uint32_t)(lane & 7);
    uint32_t k_loc = (grp & 1) * 8 + sub;
    uint32_t n_loc = (grp >> 1) * 8;
    uint32_t b_base = tb + OFF_B + k_loc * RSBB2 + (wn * 32 + n_loc) * 2;

#pragma unroll
    for (int kk = 0; kk < 4; kk++) {
        uint32_t ah[2][4];
#pragma unroll
        for (int mf = 0; mf < 2; mf++)
            ldm_x4(a_base + mf * 16 * RSBA + kk * 32, ah[mf]);
#pragma unroll
        for (int p = 0; p < 2; p++) {
            uint32_t br[4];
            ldm_x4t(b_base + kk * 16 * RSBB2 + p * 32, br);
#pragma unroll
            for (int q = 0; q < 2; q++) {
                int ni = p * 2 + q;
#pragma unroll
                for (int mi = 0; mi < 2; mi++)
                    mma16816(acc[mi][ni], ah[mi], br[2 * q], br[2 * q + 1]);
            }
        }
    }
}

// ================= GEMM 1 (+ concurrent W2 cvt plane at z==8) =================
__global__ void __launch_bounds__(128, 2) k_gemm1(const float* __restrict__ b1,
                                                  const float4* __restrict__ W2) {
    if (blockIdx.z == NEXP) {
        int bid = blockIdx.y * gridDim.x + blockIdx.x;      // 0..1023
        int idx = bid * 128 + threadIdx.x;
        const int TOT = W2_ELEMS / 8;                       // 1048576
        for (int i = idx; i < TOT; i += 1024 * 128)
            ((uint4*)g_w2)[i] = cvt8(W2[2 * i], W2[2 * i + 1]);
        return;
    }

    int s = blockIdx.z;
    int cnt = (s == 0) ? NTOK : g_cnt[s];
    int m0 = blockIdx.x * BM;
    if (m0 >= cnt) return;
    int n0 = blockIdx.y * 128;

    extern __shared__ char smem[];
    uint32_t sb = smem_u32(smem);
    int t = threadIdx.x;
    int wid = t >> 5, lane = t & 31;
    int wm = wid >> 1, wn = wid & 1;
    int* toks = (int*)smem;

    if (t < BM) {
        int m = m0 + t;
        toks[t] = (m < cnt) ? ((s == 0) ? m : g_list[s * NTOK + m]) : 0;
    }
    __syncthreads();

    auto load_chunk = [&](int st, int k0) {
        uint32_t base = sb + SM_TILES + st * STAGE1;
#pragma unroll
        for (int i = 0; i < 4; i++) {   // A: 64 rows x 8 segs = 512
            int id = i * 128 + t;
            int row = id >> 3, seg = id & 7;
            uint32_t d = base + OFF_A + row * RSBA + seg * 16;
            size_t aoff = (size_t)toks[row] * DDIM + k0 + seg * 8;
            cpa16(d, g_xa + aoff);
        }
#pragma unroll
        for (int i = 0; i < 8; i++) {   // B: 64 k-rows x 16 segs = 1024
            int id = i * 128 + t;
            int row = id >> 4, seg = id & 15;
            uint32_t d = base + OFF_B + row * RSBB + seg * 16;
            size_t boff = ((size_t)s * DDIM + k0 + row) * HDIM + n0 + seg * 8;
            cpa16(d, g_w1 + boff);
        }
        CPA_COMMIT();
    };

    float acc[2][8][4];
#pragma unroll
    for (int mi = 0; mi < 2; mi++)
#pragma unroll
        for (int ni = 0; ni < 8; ni++)
#pragma unroll
            for (int q = 0; q < 4; q++) acc[mi][ni][q] = 0.f;

    const int CH = DDIM / 64;   // 8
    load_chunk(0, 0);
    load_chunk(1, 64);
    for (int c = 0; c < CH; c++) {
        CPA_WAIT1();
        __syncthreads();
        if (c + 2 < CH) load_chunk((c + 2) % NSTG, (c + 2) * 64);
        else            CPA_COMMIT();
        gemm1_chunk(sb + SM_TILES + (c % NSTG) * STAGE1, wm, wn, lane, acc);
    }

    const float* bp = b1 + (size_t)s * HDIM;
#pragma unroll
    for (int mi = 0; mi < 2; mi++) {
        int mA = m0 + wm * 32 + mi * 16 + (lane >> 2);
        int mB = mA + 8;
        size_t rA = ((size_t)s * NTOK + mA) * HDIM;
        size_t rB = ((size_t)s * NTOK + mB) * HDIM;
        bool vA = mA < cnt, vB = mB < cnt;
#pragma unroll
        for (int ni = 0; ni < 8; ni++) {
            int col = n0 + wn * 64 + ni * 8 + 2 * (lane & 3);
            float bc0 = __ldg(bp + col), bc1 = __ldg(bp + col + 1);
            if (vA) {
                float v0 = fmaxf(acc[mi][ni][0] + bc0, 0.f);
                float v1 = fmaxf(acc[mi][ni][1] + bc1, 0.f);
                *(uint32_t*)(g_ha + rA + col) = pack2h(__float2half(v0), __float2half(v1));
            }
            if (vB) {
                float v0 = fmaxf(acc[mi][ni][2] + bc0, 0.f);
                float v1 = fmaxf(acc[mi][ni][3] + bc1, 0.f);
                *(uint32_t*)(g_ha + rB + col) = pack2h(__float2half(v0), __float2half(v1));
            }
        }
    }
}

// ================= GEMM 2: BM=64, BN=64, warp tile 32x32 =================
__global__ void __launch_bounds__(128, 2) k_gemm2(const float* __restrict__ b2,
                                                  const float* __restrict__ fw) {
    int s = blockIdx.z;
    int cnt = (s == 0) ? NTOK : g_cnt[s];
    int m0 = blockIdx.x * BM;
    if (m0 >= cnt) return;
    int n0 = blockIdx.y * 64;

    extern __shared__ char smem[];
    uint32_t sb = smem_u32(smem);
    int t = threadIdx.x;
    int wid = t >> 5, lane = t & 31;
    int wm = wid >> 1, wn = wid & 1;
    float* scl = (float*)smem;

    if (t < BM) {
        int m = m0 + t;
        scl[t] = (m < cnt) ? ((s == 0) ? BETA_FIXED * fw[0] : g_scale[s * NTOK + m]) : 0.f;
    }
    __syncthreads();

    auto load_chunk = [&](int st, int k0) {
        uint32_t base = sb + SM_TILES + st * STAGE2;
#pragma unroll
        for (int i = 0; i < 4; i++) {   // A: 64 rows x 8 segs
            int id = i * 128 + t;
            int row = id >> 3, seg = id & 7;
            uint32_t d = base + OFF_A + row * RSBA + seg * 16;
            size_t aoff = ((size_t)s * NTOK + m0 + row) * HDIM + k0 + seg * 8;
            cpa16(d, g_ha + aoff);
        }
#pragma unroll
        for (int i = 0; i < 4; i++) {   // B: 64 k-rows x 8 segs
            int id = i * 128 + t;
            int row = id >> 3, seg = id & 7;
            uint32_t d = base + OFF_B + row * RSBB2 + seg * 16;
            size_t boff = ((size_t)s * HDIM + k0 + row) * DDIM + n0 + seg * 8;
            cpa16(d, g_w2 + boff);
        }
        CPA_COMMIT();
    };

    float acc[2][4][4];
#pragma unroll
    for (int mi = 0; mi < 2; mi++)
#pragma unroll
        for (int ni = 0; ni < 4; ni++)
#pragma unroll
            for (int q = 0; q < 4; q++) acc[mi][ni][q] = 0.f;

    const int CH = HDIM / 64;   // 32
    load_chunk(0, 0);
    load_chunk(1, 64);
    for (int c = 0; c < CH; c++) {
        CPA_WAIT1();
        __syncthreads();
        if (c + 2 < CH) load_chunk((c + 2) % NSTG, (c + 2) * 64);
        else            CPA_COMMIT();
        gemm2_chunk(sb + SM_TILES + (c % NSTG) * STAGE2, wm, wn, lane, acc);
    }

    const float* bp = b2 + (size_t)s * DDIM;
#pragma unroll
    for (int mi = 0; mi < 2; mi++) {
        int mloc = wm * 32 + mi * 16 + (lane >> 2);
        int mA = m0 + mloc, mB = mA + 8;
        float scA = scl[mloc], scB = scl[mloc + 8];
        size_t rA = ((size_t)s * NTOK + mA) * DDIM;
        size_t rB = ((size_t)s * NTOK + mB) * DDIM;
        bool vA = mA < cnt, vB = mB < cnt;
#pragma unroll
        for (int ni = 0; ni < 4; ni++) {
            int col = n0 + wn * 32 + ni * 8 + 2 * (lane & 3);
            float bc0 = __ldg(bp + col), bc1 = __ldg(bp + col + 1);
            if (vA) {
                float2 v;
                v.x = (acc[mi][ni][0] + bc0) * scA;
                v.y = (acc[mi][ni][1] + bc1) * scA;
                *(float2*)(g_Y + rA + col) = v;
            }
            if (vB) {
                float2 v;
                v.x = (acc[mi][ni][2] + bc0) * scB;
                v.y = (acc[mi][ni][3] + bc1) * scB;
                *(float2*)(g_Y + rB + col) = v;
            }
        }
    }
}

// ================= combine (+ fused aux losses, + counter re-zero) =================
__global__ void k_combine(float* __restrict__ out, long out_size) {
    int n = blockIdx.x;
    int t = threadIdx.x;
    if (n == 0 && t == 0) {
        float lbl = 0.f, ent = 0.f;
#pragma unroll
        for (int j = 0; j < NC; j++) {
            float imp = g_imp[j] / (float)NTOK;
            float d = imp - (1.0f / NC);
            lbl += d * d;
            ent -= imp * logf(fmaxf(imp, 1e-8f));
        }
        lbl *= (1.0f / NC);
        long base = (long)NTOK * DDIM;
        if (base < out_size)     out[base]     = lbl;
        if (base + 1 < out_size) out[base + 1] = ent;
#pragma unroll
        for (int j = 0; j < NC; j++) g_imp[j] = 0.f;
#pragma unroll
        for (int j = 0; j < NEXP; j++) g_cnt[j] = 0;
    }
    const float4* y0 = (const float4*)(g_Y + (size_t)n * DDIM);
    int pA = g_pos[2 * n], pB = g_pos[2 * n + 1];
    const float4* yA = (const float4*)(g_Y + (size_t)pA * DDIM);
    const float4* yB = (const float4*)(g_Y + (size_t)pB * DDIM);
    float4 a = y0[t], b = yA[t], c = yB[t];
    float4 r;
    r.x = a.x + b.x + c.x;
    r.y = a.y + b.y + c.y;
    r.z = a.z + b.z + c.z;
    r.w = a.w + b.w + c.w;
    ((float4*)(out + (size_t)n * DDIM))[t] = r;
}

// ================= launch =================
extern "C" void kernel_launch(void* const* d_in, const int* in_sizes, int n_in,
                              void* d_out, int out_size) {
    const float* x  = (const float*)d_in[0];
    const float* rW = (const float*)d_in[1];
    const float* rb = (const float*)d_in[2];
    const float* W1 = (const float*)d_in[3];
    const float* b1 = (const float*)d_in[4];
    const float* W2 = (const float*)d_in[5];
    const float* b2 = (const float*)d_in[6];
    const float* fw = (const float*)d_in[7];
    float* out = (float*)d_out;
    long osz = (long)out_size;

    cudaFuncSetAttribute(k_gemm1, cudaFuncAttributeMaxDynamicSharedMemorySize, SMEM1);
    cudaFuncSetAttribute(k_gemm2, cudaFuncAttributeMaxDynamicSharedMemorySize, SMEM2);

    k_prep<<<RTR_BLOCKS + CVT1_BLOCKS, 256>>>(x, rW, rb, (const float4*)W1, out, osz);
    k_gemm1<<<dim3(NTOK / BM, 16, NEXP + 1), 128, SMEM1>>>(b1, (const float4*)W2);
    k_gemm2<<<dim3(NTOK / BM, 8, NEXP), 128, SMEM2>>>(b2, fw);
    k_combine<<<NTOK, 128>>>(out, osz);
}

// round 16
// speedup vs baseline: 1.0678x; 1.0678x over previous
#include <cuda_runtime.h>
#include <cuda_fp16.h>
#include <math.h>
#include <cstdint>

#define NTOK 4096
#define DDIM 512
#define HDIM 2048
#define NEXP 8
#define NC 7
#define BETA_FIXED (1.0f/3.0f)
#define BETA_DYN   (2.0f/3.0f)

// ================= scratch (static device globals) =================
__device__ __half g_xa[NTOK * DDIM];                 // activations fp16
__device__ __half g_w1[NEXP * DDIM * HDIM];          // [E][D][H] fp16
__device__ __half g_w2[NEXP * HDIM * DDIM];          // [E][H][D] fp16
__device__ __half g_ha[(size_t)NEXP * NTOK * HDIM];  // hidden fp16
__device__ float g_Y[(size_t)NEXP * NTOK * DDIM];
__device__ int   g_list[NEXP * NTOK];
__device__ float g_scale[NEXP * NTOK];
__device__ int   g_pos[NTOK * 2];
__device__ int   g_cnt[NEXP];    // zero at module load; k_combine re-zeroes after use
__device__ float g_imp[NC];      // idem

// ================= helpers =================
__device__ __forceinline__ uint32_t smem_u32(const void* p) {
    uint32_t a;
    asm("{ .reg .u64 t; cvta.to.shared.u64 t, %1; cvt.u32.u64 %0, t; }" : "=r"(a) : "l"(p));
    return a;
}
__device__ __forceinline__ void cpa16(uint32_t dst, const void* src) {
    asm volatile("cp.async.cg.shared.global [%0], [%1], 16;" :: "r"(dst), "l"(src));
}
#define CPA_COMMIT() asm volatile("cp.async.commit_group;" ::: "memory")
#define CPA_WAIT1()  asm volatile("cp.async.wait_group 1;" ::: "memory")

__device__ __forceinline__ void ldm_x4(uint32_t addr, uint32_t* r) {
    asm volatile("ldmatrix.sync.aligned.m8n8.x4.shared.b16 {%0,%1,%2,%3}, [%4];"
        : "=r"(r[0]), "=r"(r[1]), "=r"(r[2]), "=r"(r[3]) : "r"(addr));
}
__device__ __forceinline__ void ldm_x4t(uint32_t addr, uint32_t* r) {
    asm volatile("ldmatrix.sync.aligned.m8n8.x4.trans.shared.b16 {%0,%1,%2,%3}, [%4];"
        : "=r"(r[0]), "=r"(r[1]), "=r"(r[2]), "=r"(r[3]) : "r"(addr));
}
__device__ __forceinline__ void mma16816(float* c, const uint32_t* a, uint32_t b0, uint32_t b1) {
    asm volatile("mma.sync.aligned.m16n8k16.row.col.f32.f16.f16.f32 "
        "{%0,%1,%2,%3}, {%4,%5,%6,%7}, {%8,%9}, {%0,%1,%2,%3};"
        : "+f"(c[0]), "+f"(c[1]), "+f"(c[2]), "+f"(c[3])
        : "r"(a[0]), "r"(a[1]), "r"(a[2]), "r"(a[3]), "r"(b0), "r"(b1));
}
__device__ __forceinline__ uint32_t pack2h(__half a, __half b) {
    return ((uint32_t)__half_as_ushort(b) << 16) | __half_as_ushort(a);
}
__device__ __forceinline__ uint4 cvt8(float4 v0, float4 v1) {
    uint4 p;
    p.x = pack2h(__float2half(v0.x), __float2half(v0.y));
    p.y = pack2h(__float2half(v0.z), __float2half(v0.w));
    p.z = pack2h(__float2half(v1.x), __float2half(v1.y));
    p.w = pack2h(__float2half(v1.z), __float2half(v1.w));
    return p;
}

// ===== gemm1 smem: A 128x144B | B(64k x 128n) 272B rows =====
#define RSBA 144
#define RSBB 272
#define BM 128
#define OFF_A  0
#define OFF_B  (BM * RSBA)                       // 18432
#define STAGE1 (BM * RSBA + 64 * RSBB)           // 35840
#define NSTG 3
#define SM_TILES 1024
#define SMEM1 (SM_TILES + NSTG * STAGE1)         // 108544 -> 2 CTAs/SM

// ===== gemm2 smem: A 128x144B | B(64k x 64n) 144B rows =====
#define RSBB2 144
#define STAGE2 (BM * RSBA + 64 * RSBB2)          // 27648
#define SMEM2 (SM_TILES + NSTG * STAGE2)         // 83968 -> 2 CTAs/SM

#define W1_ELEMS (NEXP * DDIM * HDIM)
#define W2_ELEMS (NEXP * HDIM * DDIM)
#define RTR_BLOCKS (NTOK / 8)                    // 512
#define CVT1_BLOCKS 1024

// ================= fused prep: router (+x->fp16) | W1 fp32->fp16 =============
__global__ void k_prep(const float* __restrict__ x,
                       const float* __restrict__ rW,
                       const float* __restrict__ rb,
                       const float4* __restrict__ W1,
                       float* __restrict__ out, long out_size) {
    int t = threadIdx.x;
    if (blockIdx.x >= RTR_BLOCKS) {
        int idx = (blockIdx.x - RTR_BLOCKS) * blockDim.x + t;
        const int TOT = W1_ELEMS / 8;
        for (int i = idx; i < TOT; i += CVT1_BLOCKS * 256)
            ((uint4*)g_w1)[i] = cvt8(W1[2 * i], W1[2 * i + 1]);
        return;
    }

    __shared__ float imp_s[NC];
    if (t < NC) imp_s[t] = 0.f;
    __syncthreads();

    int w = t >> 5, lane = t & 31;
    int n = blockIdx.x * 8 + w;

    float acc[NC];
#pragma unroll
    for (int j = 0; j < NC; j++) acc[j] = 0.f;

    const float* xr = x + (size_t)n * DDIM;
    __half* xout = g_xa + (size_t)n * DDIM;
    for (int k = lane; k < DDIM; k += 32) {
        float xv = xr[k];
        xout[k] = __float2half(xv);
        const float* wr = rW + (size_t)k * NC;
#pragma unroll
        for (int j = 0; j < NC; j++) acc[j] += xv * wr[j];
    }
#pragma unroll
    for (int j = 0; j < NC; j++) {
#pragma unroll
        for (int off = 16; off > 0; off >>= 1)
            acc[j] += __shfl_xor_sync(0xffffffffu, acc[j], off);
        acc[j] += rb[j];
    }

    if (lane == 0) {
        float m = acc[0];
#pragma unroll
        for (int j = 1; j < NC; j++) m = fmaxf(m, acc[j]);
        float p[NC], s = 0.f;
#pragma unroll
        for (int j = 0; j < NC; j++) { p[j] = __expf(acc[j] - m); s += p[j]; }
        float inv = 1.f / s;
#pragma unroll
        for (int j = 0; j < NC; j++) atomicAdd(&imp_s[j], p[j] * inv);

        int i1 = 0;
#pragma unroll
        for (int j = 1; j < NC; j++) if (acc[j] > acc[i1]) i1 = j;
        int i2 = (i1 == 0) ? 1 : 0;
#pragma unroll
        for (int j = 0; j < NC; j++) if (j != i1 && acc[j] > acc[i2]) i2 = j;

        float e2 = __expf(acc[i2] - acc[i1]);
        float den = 1.f / (1.f + e2);
        float gA = den, gB = e2 * den;

        int eA = i1 + 1, eB = i2 + 1;
        int rA = atomicAdd(&g_cnt[eA], 1);
        int rB = atomicAdd(&g_cnt[eB], 1);
        int rowA = eA * NTOK + rA;
        int rowB = eB * NTOK + rB;
        g_list[rowA] = n;  g_list[rowB] = n;
        g_scale[rowA] = BETA_DYN * gA;
        g_scale[rowB] = BETA_DYN * gB;
        g_pos[2 * n]     = rowA;
        g_pos[2 * n + 1] = rowB;

        long selbase = (long)NTOK * DDIM + 2;
        if (selbase + 2 * (long)NTOK <= out_size) {
            out[selbase + 2 * n]     = (float)eA;
            out[selbase + 2 * n + 1] = (float)eB;
        }
    }
    __syncthreads();
    if (t < NC) atomicAdd(&g_imp[t], imp_s[t]);
}

// ================= gemm1 compute: warp tile 64x64 =================
__device__ __forceinline__ void gemm1_chunk(
    uint32_t tb, int wm, int wn, int lane, float acc[4][8][4])
{
    uint32_t a_row = (uint32_t)((lane & 7) + ((lane >> 3) & 1) * 8);
    uint32_t a_kh  = (uint32_t)(lane >> 4);
    uint32_t a_base = tb + OFF_A + (wm * 64 + a_row) * RSBA + a_kh * 16;

    uint32_t grp = (uint32_t)(lane >> 3), sub = (uint32_t)(lane & 7);
    uint32_t k_loc = (grp & 1) * 8 + sub;
    uint32_t n_loc = (grp >> 1) * 8;
    uint32_t b_base = tb + OFF_B + k_loc * RSBB + (wn * 64 + n_loc) * 2;

#pragma unroll
    for (int kk = 0; kk < 4; kk++) {
        uint32_t ah[4][4];
#pragma unroll
        for (int mf = 0; mf < 4; mf++)
            ldm_x4(a_base + mf * 16 * RSBA + kk * 32, ah[mf]);
#pragma unroll
        for (int p = 0; p < 4; p++) {
            uint32_t br[4];
            ldm_x4t(b_base + kk * 16 * RSBB + p * 32, br);
#pragma unroll
            for (int q = 0; q < 2; q++) {
                int ni = p * 2 + q;
#pragma unroll
                for (int mi = 0; mi < 4; mi++)
                    mma16816(acc[mi][ni], ah[mi], br[2 * q], br[2 * q + 1]);
            }
        }
    }
}

// ================= gemm2 compute: warp tile 64x32 =================
__device__ __forceinline__ void gemm2_chunk(
    uint32_t tb, int wm, int wn, int lane, float acc[4][4][4])
{
    uint32_t a_row = (uint32_t)((lane & 7) + ((lane >> 3) & 1) * 8);
    uint32_t a_kh  = (uint32_t)(lane >> 4);
    uint32_t a_base = tb + OFF_A + (wm * 64 + a_row) * RSBA + a_kh * 16;

    uint32_t grp = (uint32_t)(lane >> 3), sub = (uint32_t)(lane & 7);
    uint32_t k_loc = (grp & 1) * 8 + sub;
    uint32_t n_loc = (grp >> 1) * 8;
    uint32_t b_base = tb + OFF_B + k_loc * RSBB2 + (wn * 32 + n_loc) * 2;

#pragma unroll
    for (int kk = 0; kk < 4; kk++) {
        uint32_t ah[4][4];
#pragma unroll
        for (int mf = 0; mf < 4; mf++)
            ldm_x4(a_base + mf * 16 * RSBA + kk * 32, ah[mf]);
#pragma unroll
        for (int p = 0; p < 2; p++) {
            uint32_t br[4];
            ldm_x4t(b_base + kk * 16 * RSBB2 + p * 32, br);
#pragma unroll
            for (int q = 0; q < 2; q++) {
                int ni = p * 2 + q;
#pragma unroll
                for (int mi = 0; mi < 4; mi++)
                    mma16816(acc[mi][ni], ah[mi], br[2 * q], br[2 * q + 1]);
            }
        }
    }
}

// ================= GEMM 1 (+ concurrent W2 cvt plane at z==8) =================
__global__ void __launch_bounds__(128, 2) k_gemm1(const float* __restrict__ b1,
                                                  const float4* __restrict__ W2) {
    if (blockIdx.z == NEXP) {
        int bid = blockIdx.y * gridDim.x + blockIdx.x;
        int idx = bid * 128 + threadIdx.x;
        const int TOT = W2_ELEMS / 8;
        for (int i = idx; i < TOT; i += 512 * 128)
            ((uint4*)g_w2)[i] = cvt8(W2[2 * i], W2[2 * i + 1]);
        return;
    }

    int s = blockIdx.z;
    int cnt = (s == 0) ? NTOK : g_cnt[s];
    int m0 = blockIdx.x * BM;
    if (m0 >= cnt) return;
    int n0 = blockIdx.y * 128;

    extern __shared__ char smem[];
    uint32_t sb = smem_u32(smem);
    int t = threadIdx.x;
    int wid = t >> 5, lane = t & 31;
    int wm = wid >> 1, wn = wid & 1;
    int* toks = (int*)smem;

    {
        int m = m0 + t;
        toks[t] = (m < cnt) ? ((s == 0) ? m : g_list[s * NTOK + m]) : 0;
    }
    __syncthreads();

    auto load_chunk = [&](int st, int k0) {
        uint32_t base = sb + SM_TILES + st * STAGE1;
#pragma unroll
        for (int i = 0; i < 8; i++) {
            int id = i * 128 + t;
            int row = id >> 3, seg = id & 7;
            uint32_t d = base + OFF_A + row * RSBA + seg * 16;
            size_t aoff = (size_t)toks[row] * DDIM + k0 + seg * 8;
            cpa16(d, g_xa + aoff);
        }
#pragma unroll
        for (int i = 0; i < 8; i++) {
            int id = i * 128 + t;
            int row = id >> 4, seg = id & 15;
            uint32_t d = base + OFF_B + row * RSBB + seg * 16;
            size_t boff = ((size_t)s * DDIM + k0 + row) * HDIM + n0 + seg * 8;
            cpa16(d, g_w1 + boff);
        }
        CPA_COMMIT();
    };

    float acc[4][8][4];
#pragma unroll
    for (int mi = 0; mi < 4; mi++)
#pragma unroll
        for (int ni = 0; ni < 8; ni++)
#pragma unroll
            for (int q = 0; q < 4; q++) acc[mi][ni][q] = 0.f;

    const int CH = DDIM / 64;   // 8
    load_chunk(0, 0);
    load_chunk(1, 64);
    for (int c = 0; c < CH; c++) {
        CPA_WAIT1();
        __syncthreads();
        if (c + 2 < CH) load_chunk((c + 2) % NSTG, (c + 2) * 64);
        else            CPA_COMMIT();
        gemm1_chunk(sb + SM_TILES + (c % NSTG) * STAGE1, wm, wn, lane, acc);
    }

    const float* bp = b1 + (size_t)s * HDIM;
#pragma unroll
    for (int mi = 0; mi < 4; mi++) {
        int mA = m0 + wm * 64 + mi * 16 + (lane >> 2);
        int mB = mA + 8;
        size_t rA = ((size_t)s * NTOK + mA) * HDIM;
        size_t rB = ((size_t)s * NTOK + mB) * HDIM;
        bool vA = mA < cnt, vB = mB < cnt;
#pragma unroll
        for (int ni = 0; ni < 8; ni++) {
            int col = n0 + wn * 64 + ni * 8 + 2 * (lane & 3);
            float bc0 = __ldg(bp + col), bc1 = __ldg(bp + col + 1);
            if (vA) {
                float v0 = fmaxf(acc[mi][ni][0] + bc0, 0.f);
                float v1 = fmaxf(acc[mi][ni][1] + bc1, 0.f);
                *(uint32_t*)(g_ha + rA + col) = pack2h(__float2half(v0), __float2half(v1));
            }
            if (vB) {
                float v0 = fmaxf(acc[mi][ni][2] + bc0, 0.f);
                float v1 = fmaxf(acc[mi][ni][3] + bc1, 0.f);
                *(uint32_t*)(g_ha + rB + col) = pack2h(__float2half(v0), __float2half(v1));
            }
        }
    }
}

// ================= GEMM 2: BN=64, warp tile 64x32 =================
__global__ void __launch_bounds__(128, 2) k_gemm2(const float* __restrict__ b2,
                                                  const float* __restrict__ fw) {
    int s = blockIdx.z;
    int cnt = (s == 0) ? NTOK : g_cnt[s];
    int m0 = blockIdx.x * BM;
    if (m0 >= cnt) return;
    int n0 = blockIdx.y * 64;

    extern __shared__ char smem[];
    uint32_t sb = smem_u32(smem);
    int t = threadIdx.x;
    int wid = t >> 5, lane = t & 31;
    int wm = wid >> 1, wn = wid & 1;
    float* scl = (float*)smem;

    {
        int m = m0 + t;
        scl[t] = (m < cnt) ? ((s == 0) ? BETA_FIXED * fw[0] : g_scale[s * NTOK + m]) : 0.f;
    }
    __syncthreads();

    auto load_chunk = [&](int st, int k0) {
        uint32_t base = sb + SM_TILES + st * STAGE2;
#pragma unroll
        for (int i = 0; i < 8; i++) {   // A: 128 rows x 8 segs
            int id = i * 128 + t;
            int row = id >> 3, seg = id & 7;
            uint32_t d = base + OFF_A + row * RSBA + seg * 16;
            size_t aoff = ((size_t)s * NTOK + m0 + row) * HDIM + k0 + seg * 8;
            cpa16(d, g_ha + aoff);
        }
#pragma unroll
        for (int i = 0; i < 4; i++) {   // B: 64 k-rows x 8 segs = 512 cp.async
            int id = i * 128 + t;
            int row = id >> 3, seg = id & 7;
            uint32_t d = base + OFF_B + row * RSBB2 + seg * 16;
            size_t boff = ((size_t)s * HDIM + k0 + row) * DDIM + n0 + seg * 8;
            cpa16(d, g_w2 + boff);
        }
        CPA_COMMIT();
    };

    float acc[4][4][4];
#pragma unroll
    for (int mi = 0; mi < 4; mi++)
#pragma unroll
        for (int ni = 0; ni < 4; ni++)
#pragma unroll
            for (int q = 0; q < 4; q++) acc[mi][ni][q] = 0.f;

    const int CH = HDIM / 64;   // 32
    load_chunk(0, 0);
    load_chunk(1, 64);
    for (int c = 0; c < CH; c++) {
        CPA_WAIT1();
        __syncthreads();
        if (c + 2 < CH) load_chunk((c + 2) % NSTG, (c + 2) * 64);
        else            CPA_COMMIT();
        gemm2_chunk(sb + SM_TILES + (c % NSTG) * STAGE2, wm, wn, lane, acc);
    }

    const float* bp = b2 + (size_t)s * DDIM;
#pragma unroll
    for (int mi = 0; mi < 4; mi++) {
        int mloc = wm * 64 + mi * 16 + (lane >> 2);
        int mA = m0 + mloc, mB = mA + 8;
        float scA = scl[mloc], scB = scl[mloc + 8];
        size_t rA = ((size_t)s * NTOK + mA) * DDIM;
        size_t rB = ((size_t)s * NTOK + mB) * DDIM;
        bool vA = mA < cnt, vB = mB < cnt;
#pragma unroll
        for (int ni = 0; ni < 4; ni++) {
            int col = n0 + wn * 32 + ni * 8 + 2 * (lane & 3);
            float bc0 = __ldg(bp + col), bc1 = __ldg(bp + col + 1);
            if (vA) {
                float2 v;
                v.x = (acc[mi][ni][0] + bc0) * scA;
                v.y = (acc[mi][ni][1] + bc1) * scA;
                *(float2*)(g_Y + rA + col) = v;
            }
            if (vB) {
                float2 v;
                v.x = (acc[mi][ni][2] + bc0) * scB;
                v.y = (acc[mi][ni][3] + bc1) * scB;
                *(float2*)(g_Y + rB + col) = v;
            }
        }
    }
}

// ================= combine: 2 tokens per block (+ aux losses, + re-zero) =========
__global__ void k_combine(float* __restrict__ out, long out_size) {
    int t = threadIdx.x;                       // 256 threads
    int n = blockIdx.x * 2 + (t >> 7);         // 2 tokens per block
    int tt = t & 127;
    if (blockIdx.x == 0 && t == 0) {
        float lbl = 0.f, ent = 0.f;
#pragma unroll
        for (int j = 0; j < NC; j++) {
            float imp = g_imp[j] / (float)NTOK;
            float d = imp - (1.0f / NC);
            lbl += d * d;
            ent -= imp * logf(fmaxf(imp, 1e-8f));
        }
        lbl *= (1.0f / NC);
        long base = (long)NTOK * DDIM;
        if (base < out_size)     out[base]     = lbl;
        if (base + 1 < out_size) out[base + 1] = ent;
#pragma unroll
        for (int j = 0; j < NC; j++) g_imp[j] = 0.f;
#pragma unroll
        for (int j = 0; j < NEXP; j++) g_cnt[j] = 0;
    }
    int pA = g_pos[2 * n], pB = g_pos[2 * n + 1];
    const float4* y0 = (const float4*)(g_Y + (size_t)n * DDIM);
    const float4* yA = (const float4*)(g_Y + (size_t)pA * DDIM);
    const float4* yB = (const float4*)(g_Y + (size_t)pB * DDIM);
    float4 a = y0[tt], b = yA[tt], c = yB[tt];
    float4 r;
    r.x = a.x + b.x + c.x;
    r.y = a.y + b.y + c.y;
    r.z = a.z + b.z + c.z;
    r.w = a.w + b.w + c.w;
    ((float4*)(out + (size_t)n * DDIM))[tt] = r;
}

// ================= launch =================
extern "C" void kernel_launch(void* const* d_in, const int* in_sizes, int n_in,
                              void* d_out, int out_size) {
    const float* x  = (const float*)d_in[0];
    const float* rW = (const float*)d_in[1];
    const float* rb = (const float*)d_in[2];
    const float* W1 = (const float*)d_in[3];
    const float* b1 = (const float*)d_in[4];
    const float* W2 = (const float*)d_in[5];
    const float* b2 = (const float*)d_in[6];
    const float* fw = (const float*)d_in[7];
    float* out = (float*)d_out;
    long osz = (long)out_size;

    cudaFuncSetAttribute(k_gemm1, cudaFuncAttributeMaxDynamicSharedMemorySize, SMEM1);
    cudaFuncSetAttribute(k_gemm2, cudaFuncAttributeMaxDynamicSharedMemorySize, SMEM2);

    k_prep<<<RTR_BLOCKS + CVT1_BLOCKS, 256>>>(x, rW, rb, (const float4*)W1, out, osz);
    k_gemm1<<<dim3(NTOK / BM, 16, NEXP + 1), 128, SMEM1>>>(b1, (const float4*)W2);
    k_gemm2<<<dim3(NTOK / BM, 8, NEXP), 128, SMEM2>>>(b2, fw);
    k_combine<<<NTOK / 2, 256>>>(out, osz);
}